// round 5
// baseline (speedup 1.0000x reference)
#include <cuda_runtime.h>

#define N_NODES 100000
#define N_EDGES 1600000
#define IN_DIM  256
#define OUT_DIM 128
#define BATCH   8192
#define CAP     192
#define SLOPE   0.1f
#define EPS     1e-8f

#define NB_INIT 391   // ceil(100000/256)

// ---------------- static device scratch (no runtime allocation) ----------------
__device__ int   g_is64;
__device__ float g_v1[IN_DIM];           // W @ a[:128]
__device__ float g_v2[IN_DIM];           // W @ a[128:]
__device__ float g_c1, g_c2;             // b.a[:128], b.a[128:]
__device__ int   g_slot[N_NODES];        // node -> representative batch slot
__device__ int   g_cnt[BATCH];
__device__ float g_ssrc[BATCH];
__device__ int   g_gc[BATCH * CAP];
__device__ __align__(16) float g_agg [BATCH * IN_DIM];   // partial (warp-half 0)
__device__ __align__(16) float g_agg2[BATCH * IN_DIM];   // partial (warp-half 1)
__device__ float g_denom [BATCH];
__device__ float g_denom2[BATCH];

__device__ __forceinline__ int load_idx(const void* p, int i, int is64) {
    if (is64) return (int)((const long long*)p)[i];
    return ((const int*)p)[i];
}

// ---------------- K_setup ----------------
__global__ __launch_bounds__(256) void k_setup(const float* __restrict__ W,
                                               const float* __restrict__ b,
                                               const float* __restrict__ a,
                                               const void* __restrict__ rp) {
    int blk = blockIdx.x;
    int t = threadIdx.x;

    if (blk < NB_INIT) {
        int i = blk * 256 + t;
        if (i < N_NODES) g_slot[i] = 0x7fffffff;
        if (i < BATCH)   g_cnt[i] = 0;
        return;
    }

    if (blk == NB_INIT) {
        const float* wrow = W + t * OUT_DIM;
        float s1 = 0.f, s2 = 0.f;
#pragma unroll 4
        for (int j = 0; j < OUT_DIM; j++) {
            float w = wrow[j];
            s1 += w * a[j];
            s2 += w * a[OUT_DIM + j];
        }
        g_v1[t] = s1;
        g_v2[t] = s2;

        __shared__ float sb1[OUT_DIM], sb2[OUT_DIM];
        if (t < OUT_DIM) {
            float bb = b[t];
            sb1[t] = bb * a[t];
            sb2[t] = bb * a[OUT_DIM + t];
        }
        __syncthreads();
        if (t == 0) {
            float t1 = 0.f, t2 = 0.f;
            for (int j = 0; j < OUT_DIM; j++) { t1 += sb1[j]; t2 += sb2[j]; }
            g_c1 = t1; g_c2 = t2;
        }
        return;
    }

    if (t < 32) {
        const long long* r64 = (const long long*)rp;
        const long long stride = (N_EDGES / 2) / 64;
        long long v0 = r64[(long long)t * stride];
        long long v1 = r64[(long long)(t + 32) * stride];
        int ok = (v0 >= 0 && v0 < N_NODES) && (v1 >= 0 && v1 < N_NODES);
        int all = __all_sync(0xffffffffu, ok);
        if (t == 0) g_is64 = all;
    }
}

// ---------------- K_mark_ssrc ----------------
__global__ __launch_bounds__(256) void k_mark_ssrc(const float* __restrict__ feats,
                                                   const void* __restrict__ bidx) {
    int gw   = (blockIdx.x * blockDim.x + threadIdx.x) >> 5;
    int lane = threadIdx.x & 31;
    if (gw >= BATCH) return;
    int node = load_idx(bidx, gw, g_is64);
    if (lane == 0) atomicMin(&g_slot[node], gw);

    const float4* row = (const float4*)(feats + (size_t)node * IN_DIM);
    float4 fA = row[lane * 2];
    float4 fB = row[lane * 2 + 1];
    int base = lane * 8;
    float s = fA.x * g_v1[base]     + fA.y * g_v1[base + 1] + fA.z * g_v1[base + 2] + fA.w * g_v1[base + 3]
            + fB.x * g_v1[base + 4] + fB.y * g_v1[base + 5] + fB.z * g_v1[base + 6] + fB.w * g_v1[base + 7];
#pragma unroll
    for (int off = 16; off; off >>= 1) s += __shfl_xor_sync(0xffffffffu, s, off);
    if (lane == 0) g_ssrc[gw] = s + g_c1;
}

// ---------------- K_edge: 4 edges / thread ----------------
__global__ __launch_bounds__(256) void k_edge(const void* __restrict__ rp,
                                              const void* __restrict__ cp) {
    int base = (blockIdx.x * blockDim.x + threadIdx.x) * 4;
    if (base >= N_EDGES) return;     // N_EDGES % 4 == 0
    int is64 = g_is64;
    int r[4];
    if (is64) {
        longlong4 rr = ((const longlong4*)rp)[base >> 2];
        r[0] = (int)rr.x; r[1] = (int)rr.y; r[2] = (int)rr.z; r[3] = (int)rr.w;
    } else {
        int4 rr = ((const int4*)rp)[base >> 2];
        r[0] = rr.x; r[1] = rr.y; r[2] = rr.z; r[3] = rr.w;
    }
    int s[4];
#pragma unroll
    for (int k = 0; k < 4; k++) s[k] = g_slot[r[k]];
#pragma unroll
    for (int k = 0; k < 4; k++) {
        if (s[k] < BATCH) {
            int c = load_idx(cp, base + k, is64);
            int pos = atomicAdd(&g_cnt[s[k]], 1);
            if (pos < CAP) g_gc[s[k] * CAP + pos] = c;
        }
    }
}

// ---------------- K_agg: 2 warps per slot (contiguous halves), 2-edge ILP each ----------------
__global__ __launch_bounds__(128) void k_agg(const float* __restrict__ feats) {
    int gw   = (blockIdx.x * blockDim.x + threadIdx.x) >> 5;
    int lane = threadIdx.x & 31;
    if (gw >= 2 * BATCH) return;
    int slot = gw >> 1;
    int half = gw & 1;
    int n = g_cnt[slot];
    if (n > CAP) n = CAP;
    int nh = (n + 1) >> 1;
    int lo = half ? nh : 0;
    int hi = half ? n  : nh;

    float* aggbuf = half ? g_agg2 : g_agg;
    float* dbuf   = half ? g_denom2 : g_denom;

    if (lo >= hi) {
        float4 z = make_float4(0.f, 0.f, 0.f, 0.f);
        float4* outz = (float4*)&aggbuf[slot * IN_DIM + lane * 8];
        outz[0] = z; outz[1] = z;
        if (lane == 0) dbuf[slot] = 0.f;
        return;
    }

    float ssrc = g_ssrc[slot] + g_c2;
    float v2a[8];
#pragma unroll
    for (int tt = 0; tt < 8; tt++) v2a[tt] = g_v2[lane * 8 + tt];

    float acc[8] = {};
    float dsum = 0.f;
    const int* gc = &g_gc[slot * CAP];
    int m = hi - lo;                     // edges this warp handles

    float4 a0, a1, b0, b1;
    {
        int ca = gc[lo];
        int cb = gc[(1 < m) ? lo + 1 : lo];
        const float4* ra = (const float4*)(feats + (size_t)ca * IN_DIM);
        const float4* rb = (const float4*)(feats + (size_t)cb * IN_DIM);
        a0 = ra[lane * 2]; a1 = ra[lane * 2 + 1];
        b0 = rb[lane * 2]; b1 = rb[lane * 2 + 1];
    }

    for (int i = 0; i < m; i += 2) {
        float4 na0 = a0, na1 = a1, nb0 = b0, nb1 = b1;
        if (i + 2 < m) {
            int ca = gc[lo + i + 2];
            int cb = gc[(i + 3 < m) ? lo + i + 3 : lo + i + 2];
            const float4* ra = (const float4*)(feats + (size_t)ca * IN_DIM);
            const float4* rb = (const float4*)(feats + (size_t)cb * IN_DIM);
            na0 = ra[lane * 2]; na1 = ra[lane * 2 + 1];
            nb0 = rb[lane * 2]; nb1 = rb[lane * 2 + 1];
        }

        float sa = a0.x * v2a[0] + a0.y * v2a[1] + a0.z * v2a[2] + a0.w * v2a[3]
                 + a1.x * v2a[4] + a1.y * v2a[5] + a1.z * v2a[6] + a1.w * v2a[7];
        float sb = b0.x * v2a[0] + b0.y * v2a[1] + b0.z * v2a[2] + b0.w * v2a[3]
                 + b1.x * v2a[4] + b1.y * v2a[5] + b1.z * v2a[6] + b1.w * v2a[7];
#pragma unroll
        for (int off = 16; off; off >>= 1) {
            sa += __shfl_xor_sync(0xffffffffu, sa, off);
            sb += __shfl_xor_sync(0xffffffffu, sb, off);
        }
        float xa = ssrc + sa;
        float xb = ssrc + sb;
        float wa = __expf(xa > 0.f ? xa : SLOPE * xa);
        float wb = __expf(xb > 0.f ? xb : SLOPE * xb);
        if (i + 1 >= m) wb = 0.f;
        dsum += wa + wb;
        acc[0] += wa * a0.x + wb * b0.x;
        acc[1] += wa * a0.y + wb * b0.y;
        acc[2] += wa * a0.z + wb * b0.z;
        acc[3] += wa * a0.w + wb * b0.w;
        acc[4] += wa * a1.x + wb * b1.x;
        acc[5] += wa * a1.y + wb * b1.y;
        acc[6] += wa * a1.z + wb * b1.z;
        acc[7] += wa * a1.w + wb * b1.w;

        a0 = na0; a1 = na1; b0 = nb0; b1 = nb1;
    }
    float4* out = (float4*)&aggbuf[slot * IN_DIM + lane * 8];
    out[0] = make_float4(acc[0], acc[1], acc[2], acc[3]);
    out[1] = make_float4(acc[4], acc[5], acc[6], acc[7]);
    if (lane == 0) dbuf[slot] = dsum;
}

// ---------------- K_gemm: sums partial buffers while filling A-tile; writes d_out ----------------
#define GBM 64
#define GBK 32
__global__ __launch_bounds__(256) void k_gemm(const float* __restrict__ W,
                                              const float* __restrict__ bvec,
                                              float* __restrict__ out) {
    __shared__ float As[GBK][GBM + 4];    // +4 keeps rows 16B-aligned for LDS.128
    __shared__ float Bs[GBK][OUT_DIM];
    int tid = threadIdx.x;
    int ty = tid >> 5;
    int tx = tid & 31;
    int rowBase = blockIdx.x * GBM;
    float acc[8][4] = {};

    for (int k0 = 0; k0 < IN_DIM; k0 += GBK) {
#pragma unroll
        for (int i = 0; i < 2; i++) {
            int f = tid + i * 256;
            int r = f >> 3;
            int kk = (f & 7) << 2;
            size_t off = (size_t)(rowBase + r) * IN_DIM + k0 + kk;
            float4 v  = *(const float4*)&g_agg[off];
            float4 v2 = *(const float4*)&g_agg2[off];
            As[kk][r]     = v.x + v2.x;
            As[kk + 1][r] = v.y + v2.y;
            As[kk + 2][r] = v.z + v2.z;
            As[kk + 3][r] = v.w + v2.w;
        }
#pragma unroll
        for (int i = 0; i < 4; i++) {
            int f = tid + i * 256;
            int kk = f >> 5;
            int cc = (f & 31) << 2;
            *(float4*)&Bs[kk][cc] = *(const float4*)&W[(size_t)(k0 + kk) * OUT_DIM + cc];
        }
        __syncthreads();
#pragma unroll
        for (int k = 0; k < GBK; k++) {
            float4 aA = *(const float4*)&As[k][ty * 8];       // LDS.128 broadcast
            float4 aB = *(const float4*)&As[k][ty * 8 + 4];
            float a0[8] = {aA.x, aA.y, aA.z, aA.w, aB.x, aB.y, aB.z, aB.w};
            float4 bb = *(const float4*)&Bs[k][tx * 4];
#pragma unroll
            for (int r = 0; r < 8; r++) {
                acc[r][0] += a0[r] * bb.x;
                acc[r][1] += a0[r] * bb.y;
                acc[r][2] += a0[r] * bb.z;
                acc[r][3] += a0[r] * bb.w;
            }
        }
        __syncthreads();
    }

    float4 bv = *(const float4*)&bvec[tx * 4];
#pragma unroll
    for (int r = 0; r < 8; r++) {
        int row = rowBase + ty * 8 + r;
        float dn = g_denom[row] + g_denom2[row];
        float inv = 1.0f / (dn + EPS);
        float4 o;
        o.x = (acc[r][0] + dn * bv.x) * inv;
        o.y = (acc[r][1] + dn * bv.y) * inv;
        o.z = (acc[r][2] + dn * bv.z) * inv;
        o.w = (acc[r][3] + dn * bv.w) * inv;
        *(float4*)&out[(size_t)row * OUT_DIM + tx * 4] = o;
    }
}

// ---------------- K_fix: copy rows for duplicate batch positions ----------------
__global__ __launch_bounds__(256) void k_fix(const void* __restrict__ bidx,
                                             float* __restrict__ out) {
    int gw   = (blockIdx.x * blockDim.x + threadIdx.x) >> 5;
    int lane = threadIdx.x & 31;
    if (gw >= BATCH) return;
    int node = load_idx(bidx, gw, g_is64);
    int slot = g_slot[node];
    if (slot == gw) return;
    float4 v = *(const float4*)&out[(size_t)slot * OUT_DIM + lane * 4];
    *(float4*)&out[(size_t)gw * OUT_DIM + lane * 4] = v;
}

// ---------------- launch ----------------
extern "C" void kernel_launch(void* const* d_in, const int* in_sizes, int n_in,
                              void* d_out, int out_size) {
    (void)in_sizes; (void)n_in; (void)out_size;
    const float* feats = (const float*)d_in[0];
    const float* W     = (const float*)d_in[1];
    const float* b     = (const float*)d_in[2];
    const float* a     = (const float*)d_in[3];
    const void*  r     = d_in[4];
    const void*  c     = d_in[5];
    const void*  bidx  = d_in[6];
    float* out = (float*)d_out;

    k_setup<<<NB_INIT + 2, 256>>>(W, b, a, r);
    k_mark_ssrc<<<BATCH / 8, 256>>>(feats, bidx);
    k_edge<<<(N_EDGES / 4 + 255) / 256, 256>>>(r, c);
    k_agg<<<(2 * BATCH) / 4, 128>>>(feats);          // 2 warps per slot
    k_gemm<<<BATCH / GBM, 256>>>(W, b, out);
    k_fix<<<BATCH / 8, 256>>>(bidx, out);
}

// round 6
// speedup vs baseline: 1.0871x; 1.0871x over previous
#include <cuda_runtime.h>

#define N_NODES 100000
#define N_EDGES 1600000
#define IN_DIM  256
#define OUT_DIM 128
#define BATCH   8192
#define CAP     192
#define SLOPE   0.1f
#define EPS     1e-8f

#define NB_INIT 391   // ceil(100000/256)

// ---------------- static device scratch ----------------
__device__ int   g_is64;
__device__ float g_v1[IN_DIM];           // W @ a[:128]
__device__ float g_v2[IN_DIM];           // W @ a[128:]
__device__ float g_c1, g_c2;             // b.a[:128], b.a[128:]
__device__ int   g_slot[N_NODES];        // node -> representative batch slot
__device__ int   g_cnt[BATCH];
__device__ int   g_rep[BATCH];           // batch position -> representative position
__device__ int   g_gc[BATCH * CAP];
__device__ __align__(16) float g_agg[BATCH * IN_DIM];
__device__ float g_denom[BATCH];

__device__ __forceinline__ int load_idx(const void* p, int i, int is64) {
    if (is64) return (int)((const long long*)p)[i];
    return ((const int*)p)[i];
}

// ---------------- K_setup: init + prep + dtype detect ----------------
__global__ __launch_bounds__(256) void k_setup(const float* __restrict__ W,
                                               const float* __restrict__ b,
                                               const float* __restrict__ a,
                                               const void* __restrict__ rp) {
    int blk = blockIdx.x;
    int t = threadIdx.x;

    if (blk < NB_INIT) {
        int i = blk * 256 + t;
        if (i < N_NODES) g_slot[i] = 0x7fffffff;
        if (i < BATCH)   g_cnt[i] = 0;
        return;
    }

    if (blk == NB_INIT) {
        const float* wrow = W + t * OUT_DIM;
        float s1 = 0.f, s2 = 0.f;
#pragma unroll 4
        for (int j = 0; j < OUT_DIM; j++) {
            float w = wrow[j];
            s1 += w * a[j];
            s2 += w * a[OUT_DIM + j];
        }
        g_v1[t] = s1;
        g_v2[t] = s2;

        __shared__ float sb1[OUT_DIM], sb2[OUT_DIM];
        if (t < OUT_DIM) {
            float bb = b[t];
            sb1[t] = bb * a[t];
            sb2[t] = bb * a[OUT_DIM + t];
        }
        __syncthreads();
        if (t == 0) {
            float t1 = 0.f, t2 = 0.f;
            for (int j = 0; j < OUT_DIM; j++) { t1 += sb1[j]; t2 += sb2[j]; }
            g_c1 = t1; g_c2 = t2;
        }
        return;
    }

    if (t < 32) {
        const long long* r64 = (const long long*)rp;
        const long long stride = (N_EDGES / 2) / 64;
        long long v0 = r64[(long long)t * stride];
        long long v1 = r64[(long long)(t + 32) * stride];
        int ok = (v0 >= 0 && v0 < N_NODES) && (v1 >= 0 && v1 < N_NODES);
        int all = __all_sync(0xffffffffu, ok);
        if (t == 0) g_is64 = all;
    }
}

// ---------------- K_mark: node -> min batch position (tiny) ----------------
__global__ __launch_bounds__(256) void k_mark(const void* __restrict__ bidx) {
    int i = blockIdx.x * blockDim.x + threadIdx.x;
    if (i >= BATCH) return;
    int node = load_idx(bidx, i, g_is64);
    atomicMin(&g_slot[node], i);
}

// ---------------- K_edge: filter + bucket, 4 edges / thread ----------------
__global__ __launch_bounds__(256) void k_edge(const void* __restrict__ rp,
                                              const void* __restrict__ cp) {
    int base = (blockIdx.x * blockDim.x + threadIdx.x) * 4;
    if (base >= N_EDGES) return;     // N_EDGES % 4 == 0
    int is64 = g_is64;
    int r[4];
    if (is64) {
        longlong4 rr = ((const longlong4*)rp)[base >> 2];
        r[0] = (int)rr.x; r[1] = (int)rr.y; r[2] = (int)rr.z; r[3] = (int)rr.w;
    } else {
        int4 rr = ((const int4*)rp)[base >> 2];
        r[0] = rr.x; r[1] = rr.y; r[2] = rr.z; r[3] = rr.w;
    }
    int s[4];
#pragma unroll
    for (int k = 0; k < 4; k++) s[k] = g_slot[r[k]];
#pragma unroll
    for (int k = 0; k < 4; k++) {
        if (s[k] < BATCH) {
            int c = load_idx(cp, base + k, is64);
            int pos = atomicAdd(&g_cnt[s[k]], 1);
            if (pos < CAP) g_gc[s[k] * CAP + pos] = c;
        }
    }
}

// ---------------- K_agg: warp per representative slot; inline ssrc; 2-edge ILP ----------------
__global__ __launch_bounds__(128) void k_agg(const float* __restrict__ feats,
                                             const void* __restrict__ bidx) {
    int gw   = (blockIdx.x * blockDim.x + threadIdx.x) >> 5;
    int lane = threadIdx.x & 31;
    if (gw >= BATCH) return;
    int node = load_idx(bidx, gw, g_is64);
    int rep = g_slot[node];
    if (lane == 0) g_rep[gw] = rep;
    if (rep != gw) return;                // duplicate position: gemm redirects via g_rep

    // ssrc = feats[node].v1 + c1  (inline; overlaps with first edge prefetch below)
    const float4* rown = (const float4*)(feats + (size_t)node * IN_DIM);
    float4 rA = rown[lane * 2];
    float4 rB = rown[lane * 2 + 1];
    int vb = lane * 8;
    float sv = rA.x * g_v1[vb]     + rA.y * g_v1[vb + 1] + rA.z * g_v1[vb + 2] + rA.w * g_v1[vb + 3]
             + rB.x * g_v1[vb + 4] + rB.y * g_v1[vb + 5] + rB.z * g_v1[vb + 6] + rB.w * g_v1[vb + 7];

    int n = g_cnt[gw];
    if (n > CAP) n = CAP;
    const int* gc = &g_gc[gw * CAP];

    float v2a[8];
#pragma unroll
    for (int tt = 0; tt < 8; tt++) v2a[tt] = g_v2[vb + tt];

    // first edge pair prefetch (issued while ssrc reduction completes)
    float4 a0, a1, b0, b1;
    if (n > 0) {
        int ca = gc[0];
        int cb = gc[(1 < n) ? 1 : 0];
        const float4* ra = (const float4*)(feats + (size_t)ca * IN_DIM);
        const float4* rb = (const float4*)(feats + (size_t)cb * IN_DIM);
        a0 = ra[lane * 2]; a1 = ra[lane * 2 + 1];
        b0 = rb[lane * 2]; b1 = rb[lane * 2 + 1];
    }

#pragma unroll
    for (int off = 16; off; off >>= 1) sv += __shfl_xor_sync(0xffffffffu, sv, off);
    float ssrc = sv + g_c1 + g_c2;

    if (n == 0) {                         // represented node with no incoming edges
        float4 z = make_float4(0.f, 0.f, 0.f, 0.f);
        float4* outz = (float4*)&g_agg[gw * IN_DIM + lane * 8];
        outz[0] = z; outz[1] = z;
        if (lane == 0) g_denom[gw] = 0.f;
        return;
    }

    float acc[8] = {};
    float dsum = 0.f;

    for (int i = 0; i < n; i += 2) {
        float4 na0 = a0, na1 = a1, nb0 = b0, nb1 = b1;
        if (i + 2 < n) {
            int ca = gc[i + 2];
            int cb = gc[(i + 3 < n) ? (i + 3) : (i + 2)];
            const float4* ra = (const float4*)(feats + (size_t)ca * IN_DIM);
            const float4* rb = (const float4*)(feats + (size_t)cb * IN_DIM);
            na0 = ra[lane * 2]; na1 = ra[lane * 2 + 1];
            nb0 = rb[lane * 2]; nb1 = rb[lane * 2 + 1];
        }

        float sa = a0.x * v2a[0] + a0.y * v2a[1] + a0.z * v2a[2] + a0.w * v2a[3]
                 + a1.x * v2a[4] + a1.y * v2a[5] + a1.z * v2a[6] + a1.w * v2a[7];
        float sb = b0.x * v2a[0] + b0.y * v2a[1] + b0.z * v2a[2] + b0.w * v2a[3]
                 + b1.x * v2a[4] + b1.y * v2a[5] + b1.z * v2a[6] + b1.w * v2a[7];
#pragma unroll
        for (int off = 16; off; off >>= 1) {
            sa += __shfl_xor_sync(0xffffffffu, sa, off);
            sb += __shfl_xor_sync(0xffffffffu, sb, off);
        }
        float xa = ssrc + sa;
        float xb = ssrc + sb;
        float wa = __expf(xa > 0.f ? xa : SLOPE * xa);
        float wb = __expf(xb > 0.f ? xb : SLOPE * xb);
        if (i + 1 >= n) wb = 0.f;
        dsum += wa + wb;
        acc[0] += wa * a0.x + wb * b0.x;
        acc[1] += wa * a0.y + wb * b0.y;
        acc[2] += wa * a0.z + wb * b0.z;
        acc[3] += wa * a0.w + wb * b0.w;
        acc[4] += wa * a1.x + wb * b1.x;
        acc[5] += wa * a1.y + wb * b1.y;
        acc[6] += wa * a1.z + wb * b1.z;
        acc[7] += wa * a1.w + wb * b1.w;

        a0 = na0; a1 = na1; b0 = nb0; b1 = nb1;
    }
    float4* out = (float4*)&g_agg[gw * IN_DIM + lane * 8];
    out[0] = make_float4(acc[0], acc[1], acc[2], acc[3]);
    out[1] = make_float4(acc[4], acc[5], acc[6], acc[7]);
    if (lane == 0) g_denom[gw] = dsum;
}

// ---------------- K_gemm: rep-indirected A rows; writes every d_out row directly ----------------
#define GBM 64
#define GBK 32
__global__ __launch_bounds__(256) void k_gemm(const float* __restrict__ W,
                                              const float* __restrict__ bvec,
                                              float* __restrict__ out) {
    __shared__ float As[GBK][GBM + 4];    // +4 keeps rows 16B-aligned for LDS.128
    __shared__ float Bs[GBK][OUT_DIM];
    __shared__ int   reps[GBM];
    __shared__ float dns[GBM];
    int tid = threadIdx.x;
    int ty = tid >> 5;
    int tx = tid & 31;
    int rowBase = blockIdx.x * GBM;

    if (tid < GBM) {
        int rp = g_rep[rowBase + tid];
        reps[tid] = rp;
        dns[tid] = g_denom[rp];
    }
    __syncthreads();

    float acc[8][4] = {};

    for (int k0 = 0; k0 < IN_DIM; k0 += GBK) {
#pragma unroll
        for (int i = 0; i < 2; i++) {
            int f = tid + i * 256;
            int r = f >> 3;
            int kk = (f & 7) << 2;
            float4 v = *(const float4*)&g_agg[(size_t)reps[r] * IN_DIM + k0 + kk];
            As[kk][r]     = v.x;
            As[kk + 1][r] = v.y;
            As[kk + 2][r] = v.z;
            As[kk + 3][r] = v.w;
        }
#pragma unroll
        for (int i = 0; i < 4; i++) {
            int f = tid + i * 256;
            int kk = f >> 5;
            int cc = (f & 31) << 2;
            *(float4*)&Bs[kk][cc] = *(const float4*)&W[(size_t)(k0 + kk) * OUT_DIM + cc];
        }
        __syncthreads();
#pragma unroll
        for (int k = 0; k < GBK; k++) {
            float4 aA = *(const float4*)&As[k][ty * 8];
            float4 aB = *(const float4*)&As[k][ty * 8 + 4];
            float a0[8] = {aA.x, aA.y, aA.z, aA.w, aB.x, aB.y, aB.z, aB.w};
            float4 bb = *(const float4*)&Bs[k][tx * 4];
#pragma unroll
            for (int r = 0; r < 8; r++) {
                acc[r][0] += a0[r] * bb.x;
                acc[r][1] += a0[r] * bb.y;
                acc[r][2] += a0[r] * bb.z;
                acc[r][3] += a0[r] * bb.w;
            }
        }
        __syncthreads();
    }

    float4 bv = *(const float4*)&bvec[tx * 4];
#pragma unroll
    for (int r = 0; r < 8; r++) {
        int lrow = ty * 8 + r;
        int row = rowBase + lrow;
        float dn = dns[lrow];
        float inv = 1.0f / (dn + EPS);
        float4 o;
        o.x = (acc[r][0] + dn * bv.x) * inv;
        o.y = (acc[r][1] + dn * bv.y) * inv;
        o.z = (acc[r][2] + dn * bv.z) * inv;
        o.w = (acc[r][3] + dn * bv.w) * inv;
        *(float4*)&out[(size_t)row * OUT_DIM + tx * 4] = o;
    }
}

// ---------------- launch ----------------
extern "C" void kernel_launch(void* const* d_in, const int* in_sizes, int n_in,
                              void* d_out, int out_size) {
    (void)in_sizes; (void)n_in; (void)out_size;
    const float* feats = (const float*)d_in[0];
    const float* W     = (const float*)d_in[1];
    const float* b     = (const float*)d_in[2];
    const float* a     = (const float*)d_in[3];
    const void*  r     = d_in[4];
    const void*  c     = d_in[5];
    const void*  bidx  = d_in[6];
    float* out = (float*)d_out;

    k_setup<<<NB_INIT + 2, 256>>>(W, b, a, r);
    k_mark<<<BATCH / 256, 256>>>(bidx);
    k_edge<<<(N_EDGES / 4 + 255) / 256, 256>>>(r, c);
    k_agg<<<BATCH / 4, 128>>>(feats, bidx);
    k_gemm<<<BATCH / GBM, 256>>>(W, b, out);
}

// round 7
// speedup vs baseline: 1.1243x; 1.0342x over previous
#include <cuda_runtime.h>

#define N_NODES 100000
#define N_EDGES 1600000
#define IN_DIM  256
#define OUT_DIM 128
#define BATCH   8192
#define CAP     192
#define SLOPE   0.1f
#define EPS     1e-8f

#define NB_INIT 391   // ceil(100000/256)

typedef unsigned long long u64;

// ---------------- f32x2 packed helpers (Blackwell dual-FMA) ----------------
__device__ __forceinline__ u64 pk2(float lo, float hi) {
    u64 d;
    asm("mov.b64 %0, {%1, %2};" : "=l"(d) : "r"(__float_as_uint(lo)), "r"(__float_as_uint(hi)));
    return d;
}
__device__ __forceinline__ void upk2(u64 v, float& lo, float& hi) {
    unsigned int a, b;
    asm("mov.b64 {%0, %1}, %2;" : "=r"(a), "=r"(b) : "l"(v));
    lo = __uint_as_float(a); hi = __uint_as_float(b);
}
__device__ __forceinline__ void fma2(u64& d, u64 a, u64 b) {
    asm("fma.rn.f32x2 %0, %1, %2, %3;" : "=l"(d) : "l"(a), "l"(b), "l"(d));
}
__device__ __forceinline__ u64 d2l(double x) { return __double_as_longlong(x); }

// ---------------- static device scratch ----------------
__device__ int   g_is64;
__device__ __align__(16) float g_v1[IN_DIM];   // W @ a[:128]
__device__ __align__(16) float g_v2[IN_DIM];   // W @ a[128:]
__device__ float g_c1, g_c2;                   // b.a[:128], b.a[128:]
__device__ int   g_slot[N_NODES];
__device__ int   g_cnt[BATCH];
__device__ int   g_rep[BATCH];
__device__ int   g_gc[BATCH * CAP];
__device__ __align__(16) float g_agg[BATCH * IN_DIM];
__device__ float g_denom[BATCH];

__device__ __forceinline__ int load_idx(const void* p, int i, int is64) {
    if (is64) return (int)((const long long*)p)[i];
    return ((const int*)p)[i];
}

// ---------------- K_setup: init + prep + dtype detect ----------------
__global__ __launch_bounds__(256) void k_setup(const float* __restrict__ W,
                                               const float* __restrict__ b,
                                               const float* __restrict__ a,
                                               const void* __restrict__ rp) {
    int blk = blockIdx.x;
    int t = threadIdx.x;

    if (blk < NB_INIT) {
        int i = blk * 256 + t;
        if (i < N_NODES) g_slot[i] = 0x7fffffff;
        if (i < BATCH)   g_cnt[i] = 0;
        return;
    }

    if (blk == NB_INIT) {
        const float* wrow = W + t * OUT_DIM;
        float s1 = 0.f, s2 = 0.f;
#pragma unroll 4
        for (int j = 0; j < OUT_DIM; j++) {
            float w = wrow[j];
            s1 += w * a[j];
            s2 += w * a[OUT_DIM + j];
        }
        g_v1[t] = s1;
        g_v2[t] = s2;

        __shared__ float sb1[OUT_DIM], sb2[OUT_DIM];
        if (t < OUT_DIM) {
            float bb = b[t];
            sb1[t] = bb * a[t];
            sb2[t] = bb * a[OUT_DIM + t];
        }
        __syncthreads();
        if (t == 0) {
            float t1 = 0.f, t2 = 0.f;
            for (int j = 0; j < OUT_DIM; j++) { t1 += sb1[j]; t2 += sb2[j]; }
            g_c1 = t1; g_c2 = t2;
        }
        return;
    }

    if (t < 32) {
        const long long* r64 = (const long long*)rp;
        const long long stride = (N_EDGES / 2) / 64;
        long long v0 = r64[(long long)t * stride];
        long long v1 = r64[(long long)(t + 32) * stride];
        int ok = (v0 >= 0 && v0 < N_NODES) && (v1 >= 0 && v1 < N_NODES);
        int all = __all_sync(0xffffffffu, ok);
        if (t == 0) g_is64 = all;
    }
}

// ---------------- K_mark ----------------
__global__ __launch_bounds__(256) void k_mark(const void* __restrict__ bidx) {
    int i = blockIdx.x * blockDim.x + threadIdx.x;
    if (i >= BATCH) return;
    int node = load_idx(bidx, i, g_is64);
    atomicMin(&g_slot[node], i);
}

// ---------------- K_edge: filter + bucket, 4 edges / thread ----------------
__global__ __launch_bounds__(256) void k_edge(const void* __restrict__ rp,
                                              const void* __restrict__ cp) {
    int base = (blockIdx.x * blockDim.x + threadIdx.x) * 4;
    if (base >= N_EDGES) return;     // N_EDGES % 4 == 0
    int is64 = g_is64;
    int r[4];
    if (is64) {
        longlong4 rr = ((const longlong4*)rp)[base >> 2];
        r[0] = (int)rr.x; r[1] = (int)rr.y; r[2] = (int)rr.z; r[3] = (int)rr.w;
    } else {
        int4 rr = ((const int4*)rp)[base >> 2];
        r[0] = rr.x; r[1] = rr.y; r[2] = rr.z; r[3] = rr.w;
    }
    int s[4];
#pragma unroll
    for (int k = 0; k < 4; k++) s[k] = g_slot[r[k]];
#pragma unroll
    for (int k = 0; k < 4; k++) {
        if (s[k] < BATCH) {
            int c = load_idx(cp, base + k, is64);
            int pos = atomicAdd(&g_cnt[s[k]], 1);
            if (pos < CAP) g_gc[s[k] * CAP + pos] = c;
        }
    }
}

// ---------------- K_agg: warp per representative slot; packed f32x2 math ----------------
__global__ __launch_bounds__(128) void k_agg(const float* __restrict__ feats,
                                             const void* __restrict__ bidx) {
    int gw   = (blockIdx.x * blockDim.x + threadIdx.x) >> 5;
    int lane = threadIdx.x & 31;
    if (gw >= BATCH) return;
    int node = load_idx(bidx, gw, g_is64);
    int rep = g_slot[node];
    if (lane == 0) g_rep[gw] = rep;
    if (rep != gw) return;

    // packed v1/v2 chunks for this lane
    u64 v1p[4], v2p[4];
#pragma unroll
    for (int t = 0; t < 4; t++) {
        v1p[t] = d2l(((const double*)g_v1)[lane * 4 + t]);
        v2p[t] = d2l(((const double*)g_v2)[lane * 4 + t]);
    }

    // ssrc = feats[node].v1 + c1 (packed dot, overlaps first edge prefetch)
    const double2* rown = (const double2*)(feats + (size_t)node * IN_DIM);
    double2 rA = rown[lane * 2];
    double2 rB = rown[lane * 2 + 1];
    u64 sv2 = 0ull;
    fma2(sv2, d2l(rA.x), v1p[0]);
    fma2(sv2, d2l(rA.y), v1p[1]);
    fma2(sv2, d2l(rB.x), v1p[2]);
    fma2(sv2, d2l(rB.y), v1p[3]);

    int n = g_cnt[gw];
    if (n > CAP) n = CAP;
    const int* gc = &g_gc[gw * CAP];

    // first edge pair prefetch
    double2 a0, a1, b0, b1;
    if (n > 0) {
        int ca = gc[0];
        int cb = gc[(1 < n) ? 1 : 0];
        const double2* ra = (const double2*)(feats + (size_t)ca * IN_DIM);
        const double2* rb = (const double2*)(feats + (size_t)cb * IN_DIM);
        a0 = ra[lane * 2]; a1 = ra[lane * 2 + 1];
        b0 = rb[lane * 2]; b1 = rb[lane * 2 + 1];
    }

    float svl, svh;
    upk2(sv2, svl, svh);
    float sv = svl + svh;
#pragma unroll
    for (int off = 16; off; off >>= 1) sv += __shfl_xor_sync(0xffffffffu, sv, off);
    float ssrc = sv + g_c1 + g_c2;

    if (n == 0) {
        double2 z = make_double2(0.0, 0.0);
        *(double2*)&g_agg[gw * IN_DIM + lane * 8] = z;
        *(double2*)&g_agg[gw * IN_DIM + lane * 8 + 4] = z;
        if (lane == 0) g_denom[gw] = 0.f;
        return;
    }

    u64 acc2[4] = {0ull, 0ull, 0ull, 0ull};
    float dsum = 0.f;

    for (int i = 0; i < n; i += 2) {
        double2 na0 = a0, na1 = a1, nb0 = b0, nb1 = b1;
        if (i + 2 < n) {
            int ca = gc[i + 2];
            int cb = gc[(i + 3 < n) ? (i + 3) : (i + 2)];
            const double2* ra = (const double2*)(feats + (size_t)ca * IN_DIM);
            const double2* rb = (const double2*)(feats + (size_t)cb * IN_DIM);
            na0 = ra[lane * 2]; na1 = ra[lane * 2 + 1];
            nb0 = rb[lane * 2]; nb1 = rb[lane * 2 + 1];
        }

        // two packed dot products (independent chains)
        u64 sa2 = 0ull, sb2 = 0ull;
        fma2(sa2, d2l(a0.x), v2p[0]);  fma2(sb2, d2l(b0.x), v2p[0]);
        fma2(sa2, d2l(a0.y), v2p[1]);  fma2(sb2, d2l(b0.y), v2p[1]);
        fma2(sa2, d2l(a1.x), v2p[2]);  fma2(sb2, d2l(b1.x), v2p[2]);
        fma2(sa2, d2l(a1.y), v2p[3]);  fma2(sb2, d2l(b1.y), v2p[3]);
        float sal, sah, sbl, sbh;
        upk2(sa2, sal, sah);
        upk2(sb2, sbl, sbh);
        float sa = sal + sah;
        float sb = sbl + sbh;
#pragma unroll
        for (int off = 16; off; off >>= 1) {
            sa += __shfl_xor_sync(0xffffffffu, sa, off);
            sb += __shfl_xor_sync(0xffffffffu, sb, off);
        }
        float xa = ssrc + sa;
        float xb = ssrc + sb;
        float wa = __expf(xa > 0.f ? xa : SLOPE * xa);
        float wb = __expf(xb > 0.f ? xb : SLOPE * xb);
        if (i + 1 >= n) wb = 0.f;
        dsum += wa + wb;

        u64 wad = pk2(wa, wa);
        u64 wbd = pk2(wb, wb);
        fma2(acc2[0], wad, d2l(a0.x));  fma2(acc2[0], wbd, d2l(b0.x));
        fma2(acc2[1], wad, d2l(a0.y));  fma2(acc2[1], wbd, d2l(b0.y));
        fma2(acc2[2], wad, d2l(a1.x));  fma2(acc2[2], wbd, d2l(b1.x));
        fma2(acc2[3], wad, d2l(a1.y));  fma2(acc2[3], wbd, d2l(b1.y));

        a0 = na0; a1 = na1; b0 = nb0; b1 = nb1;
    }
    *(double2*)&g_agg[gw * IN_DIM + lane * 8] =
        make_double2(__longlong_as_double(acc2[0]), __longlong_as_double(acc2[1]));
    *(double2*)&g_agg[gw * IN_DIM + lane * 8 + 4] =
        make_double2(__longlong_as_double(acc2[2]), __longlong_as_double(acc2[3]));
    if (lane == 0) g_denom[gw] = dsum;
}

// ---------------- K_gemm: packed f32x2 row-pair accumulators; writes d_out ----------------
#define GBM 64
#define GBK 32
__global__ __launch_bounds__(256) void k_gemm(const float* __restrict__ W,
                                              const float* __restrict__ bvec,
                                              float* __restrict__ out) {
    __shared__ float As[GBK][GBM + 4];    // rows 16B-aligned
    __shared__ float Bs[GBK][OUT_DIM];
    __shared__ int   reps[GBM];
    __shared__ float dns[GBM];
    int tid = threadIdx.x;
    int ty = tid >> 5;
    int tx = tid & 31;
    int rowBase = blockIdx.x * GBM;

    if (tid < GBM) {
        int rp = g_rep[rowBase + tid];
        reps[tid] = rp;
        dns[tid] = g_denom[rp];
    }
    __syncthreads();

    // acc2[rp][c] = packed (row 2rp, row 2rp+1) for column tx*4+c
    u64 acc2[4][4] = {};

    for (int k0 = 0; k0 < IN_DIM; k0 += GBK) {
#pragma unroll
        for (int i = 0; i < 2; i++) {
            int f = tid + i * 256;
            int r = f >> 3;
            int kk = (f & 7) << 2;
            float4 v = *(const float4*)&g_agg[(size_t)reps[r] * IN_DIM + k0 + kk];
            As[kk][r]     = v.x;
            As[kk + 1][r] = v.y;
            As[kk + 2][r] = v.z;
            As[kk + 3][r] = v.w;
        }
#pragma unroll
        for (int i = 0; i < 4; i++) {
            int f = tid + i * 256;
            int kk = f >> 5;
            int cc = (f & 31) << 2;
            *(float4*)&Bs[kk][cc] = *(const float4*)&W[(size_t)(k0 + kk) * OUT_DIM + cc];
        }
        __syncthreads();
#pragma unroll
        for (int k = 0; k < GBK; k++) {
            double2 aA = *(const double2*)&As[k][ty * 8];       // pairs (0,1),(2,3)
            double2 aB = *(const double2*)&As[k][ty * 8 + 4];   // pairs (4,5),(6,7)
            u64 ap[4] = {d2l(aA.x), d2l(aA.y), d2l(aB.x), d2l(aB.y)};
            float4 bb = *(const float4*)&Bs[k][tx * 4];
            u64 bd0 = pk2(bb.x, bb.x);
            u64 bd1 = pk2(bb.y, bb.y);
            u64 bd2 = pk2(bb.z, bb.z);
            u64 bd3 = pk2(bb.w, bb.w);
#pragma unroll
            for (int rp = 0; rp < 4; rp++) {
                fma2(acc2[rp][0], ap[rp], bd0);
                fma2(acc2[rp][1], ap[rp], bd1);
                fma2(acc2[rp][2], ap[rp], bd2);
                fma2(acc2[rp][3], ap[rp], bd3);
            }
        }
        __syncthreads();
    }

    float4 bv = *(const float4*)&bvec[tx * 4];
#pragma unroll
    for (int rp = 0; rp < 4; rp++) {
        float lo0, hi0, lo1, hi1, lo2, hi2, lo3, hi3;
        upk2(acc2[rp][0], lo0, hi0);
        upk2(acc2[rp][1], lo1, hi1);
        upk2(acc2[rp][2], lo2, hi2);
        upk2(acc2[rp][3], lo3, hi3);
#pragma unroll
        for (int h = 0; h < 2; h++) {
            int lrow = ty * 8 + 2 * rp + h;
            int row = rowBase + lrow;
            float dn = dns[lrow];
            float inv = 1.0f / (dn + EPS);
            float4 o;
            o.x = ((h ? hi0 : lo0) + dn * bv.x) * inv;
            o.y = ((h ? hi1 : lo1) + dn * bv.y) * inv;
            o.z = ((h ? hi2 : lo2) + dn * bv.z) * inv;
            o.w = ((h ? hi3 : lo3) + dn * bv.w) * inv;
            *(float4*)&out[(size_t)row * OUT_DIM + tx * 4] = o;
        }
    }
}

// ---------------- launch ----------------
extern "C" void kernel_launch(void* const* d_in, const int* in_sizes, int n_in,
                              void* d_out, int out_size) {
    (void)in_sizes; (void)n_in; (void)out_size;
    const float* feats = (const float*)d_in[0];
    const float* W     = (const float*)d_in[1];
    const float* b     = (const float*)d_in[2];
    const float* a     = (const float*)d_in[3];
    const void*  r     = d_in[4];
    const void*  c     = d_in[5];
    const void*  bidx  = d_in[6];
    float* out = (float*)d_out;

    k_setup<<<NB_INIT + 2, 256>>>(W, b, a, r);
    k_mark<<<BATCH / 256, 256>>>(bidx);
    k_edge<<<(N_EDGES / 4 + 255) / 256, 256>>>(r, c);
    k_agg<<<BATCH / 4, 128>>>(feats, bidx);
    k_gemm<<<BATCH / GBM, 256>>>(W, b, out);
}